// round 4
// baseline (speedup 1.0000x reference)
#include <cuda_runtime.h>
#include <cstdint>
#include <cstddef>

#define T_STEPS 1024
#define NENV    256
#define DIM     128
#define FEAT    128
#define GI_COLS 384   // 3*FEAT

typedef unsigned long long ull;

// Scratch for precomputed input projections gi = obs @ Wi + bi  : [T*N, 3F]
__device__ float g_gi[(size_t)T_STEPS * NENV * GI_COLS];

// ---- packed f32x2 helpers ------------------------------------------------
#define FMA2(d, a, b, c) \
    asm("fma.rn.f32x2 %0, %1, %2, %3;" : "=l"(d) : "l"(a), "l"(b), "l"(c))

__device__ __forceinline__ ull pack2(float lo, float hi) {
    ull r;
    asm("mov.b64 %0, {%1, %2};" : "=l"(r)
        : "r"(__float_as_uint(lo)), "r"(__float_as_uint(hi)));
    return r;
}
__device__ __forceinline__ void unpack2(float& lo, float& hi, ull v) {
    unsigned a, b;
    asm("mov.b64 {%0, %1}, %2;" : "=r"(a), "=r"(b) : "l"(v));
    lo = __uint_as_float(a);
    hi = __uint_as_float(b);
}
__device__ __forceinline__ float tanhapx(float x) {
    float y;
    asm("tanh.approx.f32 %0, %1;" : "=f"(y) : "f"(x));
    return y;
}
// sigmoid(x) = 0.5*tanh(0.5x) + 0.5   (1 MUFU instead of EX2+RCP)
__device__ __forceinline__ float sigmoidapx(float x) {
    return fmaf(0.5f, tanhapx(0.5f * x), 0.5f);
}

// ---------------------------------------------------------------------------
// Phase 1: gi = obs @ Wi + bi     (M=262144, N=384, K=128)
// BM=128, BN=128, BK=16, 256 threads. 8(m)x8(n) tile per thread, m packed
// into 4 f32x2 accumulator rows. grid = (3, 2048).
// ---------------------------------------------------------------------------
__global__ __launch_bounds__(256)
void gemm_gi_kernel(const float* __restrict__ A,
                    const float* __restrict__ B,
                    const float* __restrict__ bias) {
    __shared__ __align__(16) float As[16][128];
    __shared__ __align__(16) float Bs[16][128];

    const int t  = threadIdx.x;
    const int m0 = blockIdx.y * 128;
    const int n0 = blockIdx.x * 128;
    const int tx = t & 15;          // N direction
    const int ty = t >> 4;          // M direction

    ull acc2[4][8];                 // [m-pair][n]
    #pragma unroll
    for (int i = 0; i < 4; i++)
        #pragma unroll
        for (int j = 0; j < 8; j++) acc2[i][j] = 0ull;

    for (int k0 = 0; k0 < 128; k0 += 16) {
        #pragma unroll
        for (int i = 0; i < 2; i++) {
            int idx = t + i * 256;
            int ar  = idx >> 2;
            int ac  = (idx & 3) << 2;
            float4 v = *reinterpret_cast<const float4*>(
                A + (size_t)(m0 + ar) * 128 + k0 + ac);
            As[ac + 0][ar] = v.x;
            As[ac + 1][ar] = v.y;
            As[ac + 2][ar] = v.z;
            As[ac + 3][ar] = v.w;
        }
        #pragma unroll
        for (int i = 0; i < 2; i++) {
            int idx = t + i * 256;
            int br  = idx >> 5;
            int bc  = (idx & 31) << 2;
            float4 v = *reinterpret_cast<const float4*>(
                B + (size_t)(k0 + br) * GI_COLS + n0 + bc);
            *reinterpret_cast<float4*>(&Bs[br][bc]) = v;
        }
        __syncthreads();

        #pragma unroll
        for (int kk = 0; kk < 16; kk++) {
            const ull* ap = reinterpret_cast<const ull*>(&As[kk][ty * 8]);
            ull a0 = ap[0], a1 = ap[1], a2 = ap[2], a3 = ap[3];
            float4 bA = *reinterpret_cast<const float4*>(&Bs[kk][tx * 8]);
            float4 bB = *reinterpret_cast<const float4*>(&Bs[kk][tx * 8 + 4]);
            float bv[8] = {bA.x, bA.y, bA.z, bA.w, bB.x, bB.y, bB.z, bB.w};
            #pragma unroll
            for (int j = 0; j < 8; j++) {
                ull bd = pack2(bv[j], bv[j]);
                FMA2(acc2[0][j], a0, bd, acc2[0][j]);
                FMA2(acc2[1][j], a1, bd, acc2[1][j]);
                FMA2(acc2[2][j], a2, bd, acc2[2][j]);
                FMA2(acc2[3][j], a3, bd, acc2[3][j]);
            }
        }
        __syncthreads();
    }

    float bb[8];
    #pragma unroll
    for (int j = 0; j < 8; j++) bb[j] = bias[n0 + tx * 8 + j];

    #pragma unroll
    for (int ip = 0; ip < 4; ip++) {
        float r0[8], r1[8];
        #pragma unroll
        for (int j = 0; j < 8; j++) {
            float lo, hi;
            unpack2(lo, hi, acc2[ip][j]);
            r0[j] = lo + bb[j];
            r1[j] = hi + bb[j];
        }
        int row0 = m0 + ty * 8 + 2 * ip;
        float* C0 = g_gi + (size_t)row0 * GI_COLS + n0 + tx * 8;
        float* C1 = C0 + GI_COLS;
        *reinterpret_cast<float4*>(C0)     = make_float4(r0[0], r0[1], r0[2], r0[3]);
        *reinterpret_cast<float4*>(C0 + 4) = make_float4(r0[4], r0[5], r0[6], r0[7]);
        *reinterpret_cast<float4*>(C1)     = make_float4(r1[0], r1[1], r1[2], r1[3]);
        *reinterpret_cast<float4*>(C1 + 4) = make_float4(r1[4], r1[5], r1[6], r1[7]);
    }
}

// ---------------------------------------------------------------------------
// Phase 2: sequential GRU scan. 128 CTAs x 512 threads, 2 envs per CTA.
//
// Lane layout (k-reduction intra-warp): lane = (fsub<<2) | kg, warp w.
//   fi = w*8 + (lane>>2)  in [0,128)   kg = lane&3  (k-quarter)
// Thread holds Wh{r,z,n}[kg*32 .. +31][fi] packed as 16 f32x2 each (96 regs),
// shared across both envs. h lives in SMEM, double-buffered, in 4 padded
// 34-float chunks per env (bank-conflict-free across kg; broadcast across f).
// Per step: matvec (96 FMA2) -> 2x shfl.xor reduce -> finalize on kg==0 lanes
// (both envs) -> write hsm[buf^1] -> ONE __syncthreads.
// ---------------------------------------------------------------------------
#define CHW 34   // padded chunk width (floats); 34*4B = 136B -> kg-distinct banks

__global__ __launch_bounds__(512, 1)
void gru_scan_kernel(const float* __restrict__ hidden0,
                     const unsigned char* __restrict__ resets_raw,
                     const float* __restrict__ Whr,
                     const float* __restrict__ Whz,
                     const float* __restrict__ Whn,
                     const float* __restrict__ bhn,
                     float* __restrict__ out_final,
                     float* __restrict__ out_ys) {
    __shared__ __align__(16) float hsm[2][8 * CHW];   // [buf][(e*4+chunk)*34+m]

    const int tid  = threadIdx.x;
    const int lane = tid & 31;
    const int kg   = lane & 3;                 // k-quarter
    const int fi   = ((tid >> 5) << 3) + (lane >> 2);   // feature 0..127
    const int k0   = kg * 32;
    const int envBase = blockIdx.x * 2;

    // Detect resets dtype (int32 0/1 would have zero bytes at offsets %4!=0)
    int local = 0;
    for (int i = tid; i < 4096; i += 512)
        if ((i & 3) != 0 && resets_raw[i] != 0) local = 1;
    const bool bmode = __syncthreads_or(local);
    const int* resets_i = reinterpret_cast<const int*>(resets_raw);

    // Hidden-weight slices packed as k-pairs
    ull wr2[16], wz2[16], wn2[16];
    #pragma unroll
    for (int j = 0; j < 16; j++) {
        int k = k0 + 2 * j;
        wr2[j] = pack2(Whr[k * FEAT + fi], Whr[(k + 1) * FEAT + fi]);
        wz2[j] = pack2(Whz[k * FEAT + fi], Whz[(k + 1) * FEAT + fi]);
        wn2[j] = pack2(Whn[k * FEAT + fi], Whn[(k + 1) * FEAT + fi]);
    }
    const float bn = bhn[fi];

    // Init hsm[0] with step-0 reset pre-applied (writers: kg<2 -> e=kg, f=fi)
    if (kg < 2) {
        int e = kg, env = envBase + e;
        bool d0 = bmode ? (resets_raw[env] != 0) : (resets_i[env] != 0);
        float h0 = hidden0[env * FEAT + fi];
        hsm[0][(e * 4 + (fi >> 5)) * CHW + (fi & 31)] = d0 ? 0.0f : h0;
    }
    __syncthreads();

    const bool fin = (kg == 0);
    float finalh0 = 0.0f, finalh1 = 0.0f;

    for (int t = 0; t < T_STEPS; t++) {
        const int p = t & 1;

        // gi + next-reset prefetch (kg==0 lanes; overlaps the FMA phase)
        float gr0 = 0.f, gz0 = 0.f, gn0 = 0.f;
        float gr1 = 0.f, gz1 = 0.f, gn1 = 0.f;
        bool nd0 = false, nd1 = false;
        if (fin) {
            const float* gp = g_gi + (size_t)(t * NENV + envBase) * GI_COLS;
            gr0 = gp[fi]; gz0 = gp[FEAT + fi]; gn0 = gp[2 * FEAT + fi];
            gr1 = gp[GI_COLS + fi]; gz1 = gp[GI_COLS + FEAT + fi];
            gn1 = gp[GI_COLS + 2 * FEAT + fi];
            if (t + 1 < T_STEPS) {
                int ri = (t + 1) * NENV + envBase;
                if (bmode) { nd0 = resets_raw[ri] != 0; nd1 = resets_raw[ri + 1] != 0; }
                else       { nd0 = resets_i[ri]   != 0; nd1 = resets_i[ri + 1]   != 0; }
            }
        }

        // Packed matvec partials for both envs (shared weights)
        const ull* h0p = reinterpret_cast<const ull*>(&hsm[p][(0 * 4 + kg) * CHW]);
        const ull* h1p = reinterpret_cast<const ull*>(&hsm[p][(1 * 4 + kg) * CHW]);
        ull ar0 = 0ull, az0 = 0ull, an0 = 0ull;
        ull ar1 = 0ull, az1 = 0ull, an1 = 0ull;
        #pragma unroll
        for (int j = 0; j < 16; j++) {
            ull ha = h0p[j];
            ull hb = h1p[j];
            FMA2(ar0, ha, wr2[j], ar0);
            FMA2(az0, ha, wz2[j], az0);
            FMA2(an0, ha, wn2[j], an0);
            FMA2(ar1, hb, wr2[j], ar1);
            FMA2(az1, hb, wz2[j], az1);
            FMA2(an1, hb, wn2[j], an1);
        }
        float s[6];
        { float lo, hi;
          unpack2(lo, hi, ar0); s[0] = lo + hi;
          unpack2(lo, hi, az0); s[1] = lo + hi;
          unpack2(lo, hi, an0); s[2] = lo + hi;
          unpack2(lo, hi, ar1); s[3] = lo + hi;
          unpack2(lo, hi, az1); s[4] = lo + hi;
          unpack2(lo, hi, an1); s[5] = lo + hi; }

        // Intra-warp k-reduction across kg (bits 0-1 of lane)
        #pragma unroll
        for (int i = 0; i < 6; i++)
            s[i] += __shfl_xor_sync(0xffffffffu, s[i], 1);
        #pragma unroll
        for (int i = 0; i < 6; i++)
            s[i] += __shfl_xor_sync(0xffffffffu, s[i], 2);

        // Finalize on kg==0 lanes: both envs
        if (fin) {
            const int c = (fi >> 5), m = (fi & 31);
            // env 0
            {
                float r = sigmoidapx(gr0 + s[0]);
                float z = sigmoidapx(gz0 + s[1]);
                float n = tanhapx(gn0 + fmaf(r, s[2] + bn, 0.0f) + 0.0f * r);
                n = tanhapx(gn0 + r * (s[2] + bn));
                float hold = hsm[p][(0 * 4 + c) * CHW + m];
                float hnew = (1.0f - z) * n + z * hold;
                out_ys[(size_t)(t * NENV + envBase) * FEAT + fi] = hnew;
                hsm[p ^ 1][(0 * 4 + c) * CHW + m] = nd0 ? 0.0f : hnew;
                if (t == T_STEPS - 1) finalh0 = hnew;
            }
            // env 1
            {
                float r = sigmoidapx(gr1 + s[3]);
                float z = sigmoidapx(gz1 + s[4]);
                float n = tanhapx(gn1 + r * (s[5] + bn));
                float hold = hsm[p][(1 * 4 + c) * CHW + m];
                float hnew = (1.0f - z) * n + z * hold;
                out_ys[(size_t)((t * NENV + envBase + 1)) * FEAT + fi] = hnew;
                hsm[p ^ 1][(1 * 4 + c) * CHW + m] = nd1 ? 0.0f : hnew;
                if (t == T_STEPS - 1) finalh1 = hnew;
            }
        }
        __syncthreads();
    }

    if (fin) {
        out_final[(envBase + 0) * FEAT + fi] = finalh0;
        out_final[(envBase + 1) * FEAT + fi] = finalh1;
    }
}

// ---------------------------------------------------------------------------
// Launch
// Inputs: 0 hidden_state [N,F], 1 obs [T,N,D], 2 resets [T,N] (bool/int32),
//         3 Wi [D,3F], 4 bi [3F], 5 Whr, 6 Whz, 7 Whn [F,F], 8 bhn [F]
// Output: final_h [N,F] followed by ys [T,N,F]
// ---------------------------------------------------------------------------
extern "C" void kernel_launch(void* const* d_in, const int* in_sizes, int n_in,
                              void* d_out, int out_size) {
    const float*         hidden = (const float*)d_in[0];
    const float*         obs    = (const float*)d_in[1];
    const unsigned char* resets = (const unsigned char*)d_in[2];
    const float*         Wi     = (const float*)d_in[3];
    const float*         bi     = (const float*)d_in[4];
    const float*         Whr    = (const float*)d_in[5];
    const float*         Whz    = (const float*)d_in[6];
    const float*         Whn    = (const float*)d_in[7];
    const float*         bhn    = (const float*)d_in[8];

    float* out       = (float*)d_out;
    float* out_final = out;                       // [N*F]
    float* out_ys    = out + NENV * FEAT;         // [T*N*F]

    dim3 ggrid(GI_COLS / 128, (T_STEPS * NENV) / 128);   // (3, 2048)
    gemm_gi_kernel<<<ggrid, 256>>>(obs, Wi, bi);

    gru_scan_kernel<<<NENV / 2, 512>>>(hidden, resets, Whr, Whz, Whn, bhn,
                                       out_final, out_ys);
}

// round 7
// speedup vs baseline: 1.1266x; 1.1266x over previous
#include <cuda_runtime.h>
#include <cstdint>
#include <cstddef>

#define T_STEPS 1024
#define NENV    256
#define DIM     128
#define FEAT    128
#define GI_COLS 384   // 3*FEAT

typedef unsigned long long ull;

// Scratch for precomputed input projections gi = obs @ Wi + bi  : [T*N, 3F]
__device__ float g_gi[(size_t)T_STEPS * NENV * GI_COLS];

// ---- packed f32x2 helpers ------------------------------------------------
#define FMA2(d, a, b, c) \
    asm("fma.rn.f32x2 %0, %1, %2, %3;" : "=l"(d) : "l"(a), "l"(b), "l"(c))

__device__ __forceinline__ ull pack2(float lo, float hi) {
    ull r;
    asm("mov.b64 %0, {%1, %2};" : "=l"(r)
        : "r"(__float_as_uint(lo)), "r"(__float_as_uint(hi)));
    return r;
}
__device__ __forceinline__ void unpack2(float& lo, float& hi, ull v) {
    unsigned a, b;
    asm("mov.b64 {%0, %1}, %2;" : "=r"(a), "=r"(b) : "l"(v));
    lo = __uint_as_float(a);
    hi = __uint_as_float(b);
}
__device__ __forceinline__ float tanhapx(float x) {
    float y;
    asm("tanh.approx.f32 %0, %1;" : "=f"(y) : "f"(x));
    return y;
}
// sigmoid(x) = 0.5*tanh(0.5x) + 0.5   (1 MUFU)
__device__ __forceinline__ float sigmoidapx(float x) {
    return fmaf(0.5f, tanhapx(0.5f * x), 0.5f);
}

// ---------------------------------------------------------------------------
// Phase 1: gi = obs @ Wi + bi     (M=262144, N=384, K=128)
// BM=128, BN=128, 256 threads, 8(m,packed f32x2)x8(n) per thread.
// B tile (128x128, invariant over m-blocks) loaded ONCE into SMEM.
// A tiles (BK=16) double-buffered via register prefetch -> 1 barrier/k-tile.
// Dynamic SMEM: Bs 64KB + As 2x8KB = 80KB; 2 CTAs/SM.
// ---------------------------------------------------------------------------
__global__ __launch_bounds__(256, 2)
void gemm_gi_kernel(const float* __restrict__ A,
                    const float* __restrict__ B,
                    const float* __restrict__ bias) {
    extern __shared__ float smem[];
    float* Bs = smem;                 // [128][128]  (k-major)
    float* As = smem + 128 * 128;     // [2][16][128] (k-major, m inner)

    const int t  = threadIdx.x;
    const int m0 = blockIdx.y * 128;
    const int n0 = blockIdx.x * 128;
    const int tx = t & 15;            // N direction
    const int ty = t >> 4;            // M direction

    // ---- Load full B tile (K=128 x 128n) once: 16 float4 per thread ----
    #pragma unroll
    for (int i = 0; i < 16; i++) {
        int idx = t + i * 256;        // 0..4095 float4 slots
        int k   = idx >> 5;           // 0..127
        int nc  = (idx & 31) << 2;    // 0..124
        float4 v = *reinterpret_cast<const float4*>(
            B + (size_t)k * GI_COLS + n0 + nc);
        *reinterpret_cast<float4*>(&Bs[k * 128 + nc]) = v;
    }

    // ---- Prefetch A tile 0 into registers ----
    float4 pf[2];
    #pragma unroll
    for (int i = 0; i < 2; i++) {
        int idx = t + i * 256;
        int ar  = idx >> 2;           // m row 0..127
        int ac  = (idx & 3) << 2;     // k 0,4,8,12
        pf[i] = *reinterpret_cast<const float4*>(
            A + (size_t)(m0 + ar) * 128 + 0 + ac);
    }
    // Store tile 0 into buffer 0 (transposed As[k][m])
    #pragma unroll
    for (int i = 0; i < 2; i++) {
        int idx = t + i * 256;
        int ar  = idx >> 2;
        int ac  = (idx & 3) << 2;
        float* dst = As + 0 * 2048;
        dst[(ac + 0) * 128 + ar] = pf[i].x;
        dst[(ac + 1) * 128 + ar] = pf[i].y;
        dst[(ac + 2) * 128 + ar] = pf[i].z;
        dst[(ac + 3) * 128 + ar] = pf[i].w;
    }
    __syncthreads();

    ull acc2[4][8];                   // [m-pair][n]
    #pragma unroll
    for (int i = 0; i < 4; i++)
        #pragma unroll
        for (int j = 0; j < 8; j++) acc2[i][j] = 0ull;

    #pragma unroll 1
    for (int iter = 0; iter < 8; iter++) {
        const int p = iter & 1;

        // Prefetch next A tile (global loads fly during compute below)
        if (iter < 7) {
            int k0n = (iter + 1) * 16;
            #pragma unroll
            for (int i = 0; i < 2; i++) {
                int idx = t + i * 256;
                int ar  = idx >> 2;
                int ac  = (idx & 3) << 2;
                pf[i] = *reinterpret_cast<const float4*>(
                    A + (size_t)(m0 + ar) * 128 + k0n + ac);
            }
        }

        // Compute on buffer p against Bs rows iter*16 ..
        const float* Ab = As + p * 2048;
        #pragma unroll
        for (int kk = 0; kk < 16; kk++) {
            const int kabs = iter * 16 + kk;
            const ull* ap = reinterpret_cast<const ull*>(&Ab[kk * 128 + ty * 8]);
            ull a0 = ap[0], a1 = ap[1], a2 = ap[2], a3 = ap[3];
            const float* brow = &Bs[kabs * 128 + tx * 8];
            float4 bA = *reinterpret_cast<const float4*>(brow);
            float4 bB = *reinterpret_cast<const float4*>(brow + 4);
            float bv[8] = {bA.x, bA.y, bA.z, bA.w, bB.x, bB.y, bB.z, bB.w};
            #pragma unroll
            for (int j = 0; j < 8; j++) {
                ull bd = pack2(bv[j], bv[j]);
                FMA2(acc2[0][j], a0, bd, acc2[0][j]);
                FMA2(acc2[1][j], a1, bd, acc2[1][j]);
                FMA2(acc2[2][j], a2, bd, acc2[2][j]);
                FMA2(acc2[3][j], a3, bd, acc2[3][j]);
            }
        }

        // Store prefetched tile into the other buffer, then one barrier
        if (iter < 7) {
            float* dst = As + (p ^ 1) * 2048;
            #pragma unroll
            for (int i = 0; i < 2; i++) {
                int idx = t + i * 256;
                int ar  = idx >> 2;
                int ac  = (idx & 3) << 2;
                dst[(ac + 0) * 128 + ar] = pf[i].x;
                dst[(ac + 1) * 128 + ar] = pf[i].y;
                dst[(ac + 2) * 128 + ar] = pf[i].z;
                dst[(ac + 3) * 128 + ar] = pf[i].w;
            }
            __syncthreads();
        }
    }

    // Epilogue: add bias, store
    float bb[8];
    #pragma unroll
    for (int j = 0; j < 8; j++) bb[j] = bias[n0 + tx * 8 + j];

    #pragma unroll
    for (int ip = 0; ip < 4; ip++) {
        float r0[8], r1[8];
        #pragma unroll
        for (int j = 0; j < 8; j++) {
            float lo, hi;
            unpack2(lo, hi, acc2[ip][j]);
            r0[j] = lo + bb[j];
            r1[j] = hi + bb[j];
        }
        int row0 = m0 + ty * 8 + 2 * ip;
        float* C0 = g_gi + (size_t)row0 * GI_COLS + n0 + tx * 8;
        float* C1 = C0 + GI_COLS;
        *reinterpret_cast<float4*>(C0)     = make_float4(r0[0], r0[1], r0[2], r0[3]);
        *reinterpret_cast<float4*>(C0 + 4) = make_float4(r0[4], r0[5], r0[6], r0[7]);
        *reinterpret_cast<float4*>(C1)     = make_float4(r1[0], r1[1], r1[2], r1[3]);
        *reinterpret_cast<float4*>(C1 + 4) = make_float4(r1[4], r1[5], r1[6], r1[7]);
    }
}

// ---------------------------------------------------------------------------
// Phase 2: sequential GRU scan (proven R2 structure). 128 CTAs x 512 threads,
// 2 envs per CTA. Thread (f = tid&127, kg = tid>>7): holds W[k0..k0+31][f]
// for the 3 hidden matrices packed as 16 f32x2 k-pairs each (96 regs).
// h in SMEM; SMEM partial-sum reduction; finalize on warp-coherent kg<2.
// ---------------------------------------------------------------------------
__global__ __launch_bounds__(512, 1)
void gru_scan_kernel(const float* __restrict__ hidden0,
                     const unsigned char* __restrict__ resets_raw,
                     const float* __restrict__ Whr,
                     const float* __restrict__ Whz,
                     const float* __restrict__ Whn,
                     const float* __restrict__ bhn,
                     float* __restrict__ out_final,
                     float* __restrict__ out_ys) {
    __shared__ __align__(16) float hsm[2][FEAT];
    __shared__ float part[2][3][4][FEAT];   // [env][gate][kgroup][f]

    const int tid = threadIdx.x;
    const int f   = tid & 127;
    const int kg  = tid >> 7;       // 0..3
    const int k0  = kg * 32;
    const int envBase = blockIdx.x * 2;

    // Detect resets dtype (int32 0/1 would have zero bytes at offsets %4!=0)
    int local = 0;
    for (int i = tid; i < 4096; i += 512)
        if ((i & 3) != 0 && resets_raw[i] != 0) local = 1;
    const bool bmode = __syncthreads_or(local);
    const int* resets_i = reinterpret_cast<const int*>(resets_raw);

    // Hidden-weight slices packed as k-pairs
    ull wr2[16], wz2[16], wn2[16];
    #pragma unroll
    for (int j = 0; j < 16; j++) {
        int k = k0 + 2 * j;
        wr2[j] = pack2(Whr[k * FEAT + f], Whr[(k + 1) * FEAT + f]);
        wz2[j] = pack2(Whz[k * FEAT + f], Whz[(k + 1) * FEAT + f]);
        wn2[j] = pack2(Whn[k * FEAT + f], Whn[(k + 1) * FEAT + f]);
    }
    const float bn = bhn[f];

    // Init h with step-0 reset pre-applied
    if (kg < 2) {
        int e = kg, env = envBase + e;
        bool d0 = bmode ? (resets_raw[env] != 0) : (resets_i[env] != 0);
        float h0 = hidden0[env * FEAT + f];
        hsm[e][f] = d0 ? 0.0f : h0;
    }
    __syncthreads();

    float finalh = 0.0f;

    for (int t = 0; t < T_STEPS; t++) {
        // Prefetch gi + next-step reset flag (finalize warps only)
        float gr = 0.f, gz = 0.f, gn = 0.f;
        bool nextdone = false;
        if (kg < 2) {
            int e = kg, env = envBase + e;
            const float* gp = g_gi + (size_t)(t * NENV + env) * GI_COLS;
            gr = gp[f];
            gz = gp[FEAT + f];
            gn = gp[2 * FEAT + f];
            if (t + 1 < T_STEPS) {
                int ri = (t + 1) * NENV + env;
                nextdone = bmode ? (resets_raw[ri] != 0) : (resets_i[ri] != 0);
            }
        }

        // Packed matvec partials for both envs (shared weights)
        #pragma unroll
        for (int e = 0; e < 2; e++) {
            ull ar = 0ull, az = 0ull, an = 0ull;
            const ull* h64 = reinterpret_cast<const ull*>(&hsm[e][k0]);
            #pragma unroll
            for (int j = 0; j < 16; j++) {
                ull h2 = h64[j];
                FMA2(ar, h2, wr2[j], ar);
                FMA2(az, h2, wz2[j], az);
                FMA2(an, h2, wn2[j], an);
            }
            float lo, hi;
            unpack2(lo, hi, ar); part[e][0][kg][f] = lo + hi;
            unpack2(lo, hi, az); part[e][1][kg][f] = lo + hi;
            unpack2(lo, hi, an); part[e][2][kg][f] = lo + hi;
        }
        __syncthreads();

        // Finalize: warps with kg==0 -> env0, kg==1 -> env1 (warp-coherent)
        if (kg < 2) {
            int e = kg, env = envBase + e;
            float sr = part[e][0][0][f] + part[e][0][1][f] +
                       part[e][0][2][f] + part[e][0][3][f];
            float sz = part[e][1][0][f] + part[e][1][1][f] +
                       part[e][1][2][f] + part[e][1][3][f];
            float sn = part[e][2][0][f] + part[e][2][1][f] +
                       part[e][2][2][f] + part[e][2][3][f];
            float r = sigmoidapx(gr + sr);
            float z = sigmoidapx(gz + sz);
            float n = tanhapx(gn + r * (sn + bn));
            float hold = hsm[e][f];
            float hnew = (1.0f - z) * n + z * hold;
            out_ys[(size_t)(t * NENV + env) * FEAT + f] = hnew;
            hsm[e][f] = nextdone ? 0.0f : hnew;   // pre-apply next reset
            if (t == T_STEPS - 1) finalh = hnew;
        }
        __syncthreads();
    }

    if (kg < 2) {
        int env = envBase + kg;
        out_final[env * FEAT + f] = finalh;
    }
}

// ---------------------------------------------------------------------------
// Launch
// Inputs: 0 hidden_state [N,F], 1 obs [T,N,D], 2 resets [T,N] (bool/int32),
//         3 Wi [D,3F], 4 bi [3F], 5 Whr, 6 Whz, 7 Whn [F,F], 8 bhn [F]
// Output: final_h [N,F] followed by ys [T,N,F]
// ---------------------------------------------------------------------------
extern "C" void kernel_launch(void* const* d_in, const int* in_sizes, int n_in,
                              void* d_out, int out_size) {
    const float*         hidden = (const float*)d_in[0];
    const float*         obs    = (const float*)d_in[1];
    const unsigned char* resets = (const unsigned char*)d_in[2];
    const float*         Wi     = (const float*)d_in[3];
    const float*         bi     = (const float*)d_in[4];
    const float*         Whr    = (const float*)d_in[5];
    const float*         Whz    = (const float*)d_in[6];
    const float*         Whn    = (const float*)d_in[7];
    const float*         bhn    = (const float*)d_in[8];

    float* out       = (float*)d_out;
    float* out_final = out;                       // [N*F]
    float* out_ys    = out + NENV * FEAT;         // [T*N*F]

    // Dynamic SMEM: Bs (128*128) + As (2*16*128) floats = 80 KB
    const int smem_bytes = (128 * 128 + 2 * 16 * 128) * (int)sizeof(float);
    static int attr_set = 0;
    if (!attr_set) {
        cudaFuncSetAttribute(gemm_gi_kernel,
                             cudaFuncAttributeMaxDynamicSharedMemorySize,
                             smem_bytes);
        attr_set = 1;
    }

    dim3 ggrid(GI_COLS / 128, (T_STEPS * NENV) / 128);   // (3, 2048)
    gemm_gi_kernel<<<ggrid, 256, smem_bytes>>>(obs, Wi, bi);

    gru_scan_kernel<<<NENV / 2, 512>>>(hidden, resets, Whr, Whz, Whn, bhn,
                                       out_final, out_ys);
}

// round 8
// speedup vs baseline: 1.5849x; 1.4068x over previous
#include <cuda_runtime.h>
#include <cstdint>
#include <cstddef>

#define T_STEPS 1024
#define NENV    256
#define DIM     128
#define FEAT    128
#define GI_COLS 384   // 3*FEAT

typedef unsigned long long ull;

// Scratch for precomputed input projections gi = obs @ Wi + bi  : [T*N, 3F]
__device__ float g_gi[(size_t)T_STEPS * NENV * GI_COLS];

// ---- packed f32x2 helpers ------------------------------------------------
#define FMA2(d, a, b, c) \
    asm("fma.rn.f32x2 %0, %1, %2, %3;" : "=l"(d) : "l"(a), "l"(b), "l"(c))

__device__ __forceinline__ ull pack2(float lo, float hi) {
    ull r;
    asm("mov.b64 %0, {%1, %2};" : "=l"(r)
        : "r"(__float_as_uint(lo)), "r"(__float_as_uint(hi)));
    return r;
}
__device__ __forceinline__ void unpack2(float& lo, float& hi, ull v) {
    unsigned a, b;
    asm("mov.b64 {%0, %1}, %2;" : "=r"(a), "=r"(b) : "l"(v));
    lo = __uint_as_float(a);
    hi = __uint_as_float(b);
}
__device__ __forceinline__ float tanhapx(float x) {
    float y;
    asm("tanh.approx.f32 %0, %1;" : "=f"(y) : "f"(x));
    return y;
}
// sigmoid(x) = 0.5*tanh(0.5x) + 0.5   (1 MUFU)
__device__ __forceinline__ float sigmoidapx(float x) {
    return fmaf(0.5f, tanhapx(0.5f * x), 0.5f);
}
__device__ __forceinline__ unsigned smem_u32(const void* p) {
    unsigned a;
    asm("{ .reg .u64 t; cvta.to.shared.u64 t, %1; cvt.u32.u64 %0, t; }"
        : "=r"(a) : "l"(p));
    return a;
}
#define CP_ASYNC16(dst_u32, src_ptr) \
    asm volatile("cp.async.cg.shared.global [%0], [%1], 16;" \
                 :: "r"(dst_u32), "l"(src_ptr))
#define CP_COMMIT() asm volatile("cp.async.commit_group;")
#define CP_WAIT1()  asm volatile("cp.async.wait_group 1;")

// ---------------------------------------------------------------------------
// Phase 1: gi = obs @ Wi + bi     (M=262144, N=384, K=128)
// BM=128, BN=128, 256 threads, 8(m,packed f32x2)x8(n) per thread.
// B tile loaded once to SMEM; A tiles double-buffered; 1 barrier/k-tile.
// ---------------------------------------------------------------------------
__global__ __launch_bounds__(256, 2)
void gemm_gi_kernel(const float* __restrict__ A,
                    const float* __restrict__ B,
                    const float* __restrict__ bias) {
    extern __shared__ float smem[];
    float* Bs = smem;                 // [128][128]  (k-major)
    float* As = smem + 128 * 128;     // [2][16][128]

    const int t  = threadIdx.x;
    const int m0 = blockIdx.y * 128;
    const int n0 = blockIdx.x * 128;
    const int tx = t & 15;
    const int ty = t >> 4;

    #pragma unroll
    for (int i = 0; i < 16; i++) {
        int idx = t + i * 256;
        int k   = idx >> 5;
        int nc  = (idx & 31) << 2;
        float4 v = *reinterpret_cast<const float4*>(
            B + (size_t)k * GI_COLS + n0 + nc);
        *reinterpret_cast<float4*>(&Bs[k * 128 + nc]) = v;
    }

    float4 pf[2];
    #pragma unroll
    for (int i = 0; i < 2; i++) {
        int idx = t + i * 256;
        int ar  = idx >> 2;
        int ac  = (idx & 3) << 2;
        pf[i] = *reinterpret_cast<const float4*>(
            A + (size_t)(m0 + ar) * 128 + 0 + ac);
    }
    #pragma unroll
    for (int i = 0; i < 2; i++) {
        int idx = t + i * 256;
        int ar  = idx >> 2;
        int ac  = (idx & 3) << 2;
        float* dst = As;
        dst[(ac + 0) * 128 + ar] = pf[i].x;
        dst[(ac + 1) * 128 + ar] = pf[i].y;
        dst[(ac + 2) * 128 + ar] = pf[i].z;
        dst[(ac + 3) * 128 + ar] = pf[i].w;
    }
    __syncthreads();

    ull acc2[4][8];
    #pragma unroll
    for (int i = 0; i < 4; i++)
        #pragma unroll
        for (int j = 0; j < 8; j++) acc2[i][j] = 0ull;

    #pragma unroll 1
    for (int iter = 0; iter < 8; iter++) {
        const int p = iter & 1;
        if (iter < 7) {
            int k0n = (iter + 1) * 16;
            #pragma unroll
            for (int i = 0; i < 2; i++) {
                int idx = t + i * 256;
                int ar  = idx >> 2;
                int ac  = (idx & 3) << 2;
                pf[i] = *reinterpret_cast<const float4*>(
                    A + (size_t)(m0 + ar) * 128 + k0n + ac);
            }
        }
        const float* Ab = As + p * 2048;
        #pragma unroll
        for (int kk = 0; kk < 16; kk++) {
            const int kabs = iter * 16 + kk;
            const ull* ap = reinterpret_cast<const ull*>(&Ab[kk * 128 + ty * 8]);
            ull a0 = ap[0], a1 = ap[1], a2 = ap[2], a3 = ap[3];
            const float* brow = &Bs[kabs * 128 + tx * 8];
            float4 bA = *reinterpret_cast<const float4*>(brow);
            float4 bB = *reinterpret_cast<const float4*>(brow + 4);
            float bv[8] = {bA.x, bA.y, bA.z, bA.w, bB.x, bB.y, bB.z, bB.w};
            #pragma unroll
            for (int j = 0; j < 8; j++) {
                ull bd = pack2(bv[j], bv[j]);
                FMA2(acc2[0][j], a0, bd, acc2[0][j]);
                FMA2(acc2[1][j], a1, bd, acc2[1][j]);
                FMA2(acc2[2][j], a2, bd, acc2[2][j]);
                FMA2(acc2[3][j], a3, bd, acc2[3][j]);
            }
        }
        if (iter < 7) {
            float* dst = As + (p ^ 1) * 2048;
            #pragma unroll
            for (int i = 0; i < 2; i++) {
                int idx = t + i * 256;
                int ar  = idx >> 2;
                int ac  = (idx & 3) << 2;
                dst[(ac + 0) * 128 + ar] = pf[i].x;
                dst[(ac + 1) * 128 + ar] = pf[i].y;
                dst[(ac + 2) * 128 + ar] = pf[i].z;
                dst[(ac + 3) * 128 + ar] = pf[i].w;
            }
            __syncthreads();
        }
    }

    float bb[8];
    #pragma unroll
    for (int j = 0; j < 8; j++) bb[j] = bias[n0 + tx * 8 + j];

    #pragma unroll
    for (int ip = 0; ip < 4; ip++) {
        float r0[8], r1[8];
        #pragma unroll
        for (int j = 0; j < 8; j++) {
            float lo, hi;
            unpack2(lo, hi, acc2[ip][j]);
            r0[j] = lo + bb[j];
            r1[j] = hi + bb[j];
        }
        int row0 = m0 + ty * 8 + 2 * ip;
        float* C0 = g_gi + (size_t)row0 * GI_COLS + n0 + tx * 8;
        float* C1 = C0 + GI_COLS;
        *reinterpret_cast<float4*>(C0)     = make_float4(r0[0], r0[1], r0[2], r0[3]);
        *reinterpret_cast<float4*>(C0 + 4) = make_float4(r0[4], r0[5], r0[6], r0[7]);
        *reinterpret_cast<float4*>(C1)     = make_float4(r1[0], r1[1], r1[2], r1[3]);
        *reinterpret_cast<float4*>(C1 + 4) = make_float4(r1[4], r1[5], r1[6], r1[7]);
    }
}

// ---------------------------------------------------------------------------
// Phase 2: sequential GRU scan. 128 CTAs x 512 threads, 2 envs per CTA.
// Thread (f = tid&127, kg = tid>>7): register-resident weight slices.
// NEW: gi staged to SMEM one step ahead via cp.async (no per-step LDG on the
// critical path); resets preloaded once into a 2KB SMEM table.
// ---------------------------------------------------------------------------
__global__ __launch_bounds__(512, 1)
void gru_scan_kernel(const float* __restrict__ hidden0,
                     const unsigned char* __restrict__ resets_raw,
                     const float* __restrict__ Whr,
                     const float* __restrict__ Whz,
                     const float* __restrict__ Whn,
                     const float* __restrict__ bhn,
                     float* __restrict__ out_final,
                     float* __restrict__ out_ys) {
    __shared__ __align__(16) float hsm[2][FEAT];
    __shared__ float part[2][3][4][FEAT];       // [env][gate][kgroup][f]
    __shared__ __align__(16) float gibuf[2][2 * GI_COLS];   // [buf][e*384+g*128+f]
    __shared__ unsigned char rs2[T_STEPS * 2];  // [t][env]

    const int tid = threadIdx.x;
    const int f   = tid & 127;
    const int kg  = tid >> 7;       // 0..3
    const int k0  = kg * 32;
    const int envBase = blockIdx.x * 2;

    // Detect resets dtype (int32 0/1 would have zero bytes at offsets %4!=0)
    int local = 0;
    for (int i = tid; i < 4096; i += 512)
        if ((i & 3) != 0 && resets_raw[i] != 0) local = 1;
    const bool bmode = __syncthreads_or(local);
    const int* resets_i = reinterpret_cast<const int*>(resets_raw);

    // Kick off gi stage for t=0 into buffer 0
    const unsigned gib0 = smem_u32(&gibuf[0][0]);
    const unsigned gib1 = smem_u32(&gibuf[1][0]);
    if (tid < 192) {
        const float* src = g_gi + (size_t)envBase * GI_COLS + tid * 4;
        CP_ASYNC16(gib0 + tid * 16, src);
        CP_COMMIT();
    }

    // Preload resets table: rs2[t*2+e]
    for (int i = tid; i < T_STEPS * 2; i += 512) {
        int tt = i >> 1, e = i & 1;
        int gidx = tt * NENV + envBase + e;
        rs2[i] = bmode ? (resets_raw[gidx] != 0) : (resets_i[gidx] != 0);
    }

    // Hidden-weight slices packed as k-pairs (register resident)
    ull wr2[16], wz2[16], wn2[16];
    #pragma unroll
    for (int j = 0; j < 16; j++) {
        int k = k0 + 2 * j;
        wr2[j] = pack2(Whr[k * FEAT + f], Whr[(k + 1) * FEAT + f]);
        wz2[j] = pack2(Whz[k * FEAT + f], Whz[(k + 1) * FEAT + f]);
        wn2[j] = pack2(Whn[k * FEAT + f], Whn[(k + 1) * FEAT + f]);
    }
    const float bn = bhn[f];
    __syncthreads();   // rs2 visible

    // Init h with step-0 reset pre-applied
    if (kg < 2) {
        int e = kg, env = envBase + e;
        float h0 = hidden0[env * FEAT + f];
        hsm[e][f] = rs2[e] ? 0.0f : h0;
    }
    __syncthreads();

    float finalh = 0.0f;

    #pragma unroll 1
    for (int t = 0; t < T_STEPS; t++) {
        const int p = t & 1;

        // Stage gi for t+1 into the other buffer (fire-and-forget)
        if (tid < 192) {
            int tn = (t + 1 < T_STEPS) ? (t + 1) : t;
            const float* src =
                g_gi + ((size_t)tn * NENV + envBase) * GI_COLS + tid * 4;
            CP_ASYNC16((p ? gib0 : gib1) + tid * 16, src);
            CP_COMMIT();
        }

        // Packed matvec partials for both envs (shared weights)
        #pragma unroll
        for (int e = 0; e < 2; e++) {
            ull ar = 0ull, az = 0ull, an = 0ull;
            const ull* h64 = reinterpret_cast<const ull*>(&hsm[e][k0]);
            #pragma unroll
            for (int j = 0; j < 16; j++) {
                ull h2 = h64[j];
                FMA2(ar, h2, wr2[j], ar);
                FMA2(az, h2, wz2[j], az);
                FMA2(an, h2, wn2[j], an);
            }
            float lo, hi;
            unpack2(lo, hi, ar); part[e][0][kg][f] = lo + hi;
            unpack2(lo, hi, az); part[e][1][kg][f] = lo + hi;
            unpack2(lo, hi, an); part[e][2][kg][f] = lo + hi;
        }
        if (tid < 192) CP_WAIT1();   // gi(t) group (issued last step) done
        __syncthreads();

        // Finalize: warps kg==0 -> env0, kg==1 -> env1 (warp-coherent)
        if (kg < 2) {
            int e = kg, env = envBase + e;
            const float* gb = &gibuf[p][e * GI_COLS];
            float gr = gb[f], gz = gb[FEAT + f], gn = gb[2 * FEAT + f];
            float sr = part[e][0][0][f] + part[e][0][1][f] +
                       part[e][0][2][f] + part[e][0][3][f];
            float sz = part[e][1][0][f] + part[e][1][1][f] +
                       part[e][1][2][f] + part[e][1][3][f];
            float sn = part[e][2][0][f] + part[e][2][1][f] +
                       part[e][2][2][f] + part[e][2][3][f];
            float r = sigmoidapx(gr + sr);
            float z = sigmoidapx(gz + sz);
            float n = tanhapx(gn + r * (sn + bn));
            float hold = hsm[e][f];
            float hnew = (1.0f - z) * n + z * hold;
            out_ys[(size_t)(t * NENV + env) * FEAT + f] = hnew;
            bool nextdone = (t + 1 < T_STEPS) ? (rs2[(t + 1) * 2 + e] != 0)
                                              : false;
            hsm[e][f] = nextdone ? 0.0f : hnew;   // pre-apply next reset
            if (t == T_STEPS - 1) finalh = hnew;
        }
        __syncthreads();
    }

    if (kg < 2) {
        int env = envBase + kg;
        out_final[env * FEAT + f] = finalh;
    }
}

// ---------------------------------------------------------------------------
// Launch
// Inputs: 0 hidden_state [N,F], 1 obs [T,N,D], 2 resets [T,N] (bool/int32),
//         3 Wi [D,3F], 4 bi [3F], 5 Whr, 6 Whz, 7 Whn [F,F], 8 bhn [F]
// Output: final_h [N,F] followed by ys [T,N,F]
// ---------------------------------------------------------------------------
extern "C" void kernel_launch(void* const* d_in, const int* in_sizes, int n_in,
                              void* d_out, int out_size) {
    const float*         hidden = (const float*)d_in[0];
    const float*         obs    = (const float*)d_in[1];
    const unsigned char* resets = (const unsigned char*)d_in[2];
    const float*         Wi     = (const float*)d_in[3];
    const float*         bi     = (const float*)d_in[4];
    const float*         Whr    = (const float*)d_in[5];
    const float*         Whz    = (const float*)d_in[6];
    const float*         Whn    = (const float*)d_in[7];
    const float*         bhn    = (const float*)d_in[8];

    float* out       = (float*)d_out;
    float* out_final = out;                       // [N*F]
    float* out_ys    = out + NENV * FEAT;         // [T*N*F]

    const int smem_bytes = (128 * 128 + 2 * 16 * 128) * (int)sizeof(float);
    static int attr_set = 0;
    if (!attr_set) {
        cudaFuncSetAttribute(gemm_gi_kernel,
                             cudaFuncAttributeMaxDynamicSharedMemorySize,
                             smem_bytes);
        attr_set = 1;
    }

    dim3 ggrid(GI_COLS / 128, (T_STEPS * NENV) / 128);   // (3, 2048)
    gemm_gi_kernel<<<ggrid, 256, smem_bytes>>>(obs, Wi, bi);

    gru_scan_kernel<<<NENV / 2, 512>>>(hidden, resets, Whr, Whz, Whn, bhn,
                                       out_final, out_ys);
}

// round 10
// speedup vs baseline: 1.9310x; 1.2184x over previous
#include <cuda_runtime.h>
#include <cuda_bf16.h>
#include <cstdint>
#include <cstddef>

#define T_STEPS 1024
#define NENV    256
#define DIM     128
#define FEAT    128
#define GI_COLS 384   // 3*FEAT

typedef unsigned long long ull;

// Scratch for precomputed input projections gi = obs @ Wi + bi  : [T*N, 3F]
__device__ float g_gi[(size_t)T_STEPS * NENV * GI_COLS];

// ---- packed f32x2 helpers ------------------------------------------------
#define FMA2(d, a, b, c) \
    asm("fma.rn.f32x2 %0, %1, %2, %3;" : "=l"(d) : "l"(a), "l"(b), "l"(c))

__device__ __forceinline__ ull pack2(float lo, float hi) {
    ull r;
    asm("mov.b64 %0, {%1, %2};" : "=l"(r)
        : "r"(__float_as_uint(lo)), "r"(__float_as_uint(hi)));
    return r;
}
__device__ __forceinline__ void unpack2(float& lo, float& hi, ull v) {
    unsigned a, b;
    asm("mov.b64 {%0, %1}, %2;" : "=r"(a), "=r"(b) : "l"(v));
    lo = __uint_as_float(a);
    hi = __uint_as_float(b);
}
__device__ __forceinline__ float tanhapx(float x) {
    float y;
    asm("tanh.approx.f32 %0, %1;" : "=f"(y) : "f"(x));
    return y;
}
__device__ __forceinline__ float sigmoidapx(float x) {
    return fmaf(0.5f, tanhapx(0.5f * x), 0.5f);
}
__device__ __forceinline__ unsigned smem_u32(const void* p) {
    unsigned a;
    asm("{ .reg .u64 t; cvta.to.shared.u64 t, %1; cvt.u32.u64 %0, t; }"
        : "=r"(a) : "l"(p));
    return a;
}
#define CP_ASYNC16(dst_u32, src_ptr) \
    asm volatile("cp.async.cg.shared.global [%0], [%1], 16;" \
                 :: "r"(dst_u32), "l"(src_ptr))
#define CP_COMMIT() asm volatile("cp.async.commit_group;")
#define CP_WAIT1()  asm volatile("cp.async.wait_group 1;")

// ---- bf16 split helpers ---------------------------------------------------
__device__ __forceinline__ unsigned pkbf2(__nv_bfloat16 b0, __nv_bfloat16 b1) {
    return ((unsigned)__bfloat16_as_ushort(b1) << 16) |
           (unsigned)__bfloat16_as_ushort(b0);
}

#define MMA16816(d, a, b) \
    asm volatile("mma.sync.aligned.m16n8k16.row.col.f32.bf16.bf16.f32 " \
        "{%0,%1,%2,%3}, {%4,%5,%6,%7}, {%8,%9}, {%0,%1,%2,%3};" \
        : "+f"((d)[0]), "+f"((d)[1]), "+f"((d)[2]), "+f"((d)[3]) \
        : "r"((a)[0]), "r"((a)[1]), "r"((a)[2]), "r"((a)[3]), \
          "r"((b)[0]), "r"((b)[1]))

// ---------------------------------------------------------------------------
// Phase 1: gi = obs @ Wi + bi  via bf16 3-term split tensor-core GEMM.
//   A = obs [M=262144, K=128] fp32 -> split Ah + Al (bf16)
//   B = Wi  [K=128, N=384]   fp32 -> split Bh + Bl (bf16, transposed to [n][k])
//   A@B ~= Ah Bh + Al Bh + Ah Bl   (fp32 accumulate; rel err ~1e-5)
// CTA: 128m block, full K in SMEM, loops over 3 n-blocks of 128.
// 256 threads = 8 warps (2m x 4n), warp tile 64x32, mma m16n8k16.
// SMEM word stride 68 per row -> fragment LDS bank = (4g+q)%32, conflict-free.
// ---------------------------------------------------------------------------
#define WST 68   // row stride in 32-bit words (= 136 bf16)

__global__ __launch_bounds__(256)
void gemm_gi_bf16_kernel(const float* __restrict__ A,
                         const float* __restrict__ B,
                         const float* __restrict__ bias) {
    extern __shared__ unsigned smw[];
    unsigned* Ahi = smw;                  // [128][WST]
    unsigned* Alo = Ahi + 128 * WST;
    unsigned* Bhi = Alo + 128 * WST;      // [n][k-pairs]
    unsigned* Blo = Bhi + 128 * WST;

    const int t    = threadIdx.x;
    const int m0   = blockIdx.x * 128;
    const int warp = t >> 5;
    const int lane = t & 31;
    const int g    = lane >> 2;      // 0..7
    const int q    = lane & 3;       // 0..3
    const int wm   = warp >> 2;      // 0..1
    const int wn   = warp & 3;       // 0..3

    // ---- Fill A (obs block, full K), split hi/lo ----
    #pragma unroll
    for (int i = 0; i < 16; i++) {
        int idx = t + i * 256;            // 0..4095 float4 slots
        int m   = idx >> 5;               // 0..127
        int kc  = (idx & 31) << 2;        // 0..124
        float4 v = *reinterpret_cast<const float4*>(
            A + (size_t)(m0 + m) * 128 + kc);
        __nv_bfloat16 hx = __float2bfloat16(v.x), hy = __float2bfloat16(v.y);
        __nv_bfloat16 hz = __float2bfloat16(v.z), hw = __float2bfloat16(v.w);
        Ahi[m * WST + (kc >> 1)]     = pkbf2(hx, hy);
        Ahi[m * WST + (kc >> 1) + 1] = pkbf2(hz, hw);
        __nv_bfloat16 lx = __float2bfloat16(v.x - __bfloat162float(hx));
        __nv_bfloat16 ly = __float2bfloat16(v.y - __bfloat162float(hy));
        __nv_bfloat16 lz = __float2bfloat16(v.z - __bfloat162float(hz));
        __nv_bfloat16 lw = __float2bfloat16(v.w - __bfloat162float(hw));
        Alo[m * WST + (kc >> 1)]     = pkbf2(lx, ly);
        Alo[m * WST + (kc >> 1) + 1] = pkbf2(lz, lw);
    }

    for (int nb = 0; nb < 3; nb++) {
        const int n0 = nb * 128;
        __syncthreads();   // A ready (nb=0) / all warps done with prev B

        // ---- Fill B block transposed: Bhi[n][k2] (coalesced n reads) ----
        #pragma unroll
        for (int i = 0; i < 32; i++) {
            int idx = t + i * 256;        // 0..8191
            int n   = idx & 127;
            int k2  = idx >> 7;           // k-pair 0..63
            float x0 = B[(size_t)(2 * k2)     * GI_COLS + n0 + n];
            float x1 = B[(size_t)(2 * k2 + 1) * GI_COLS + n0 + n];
            __nv_bfloat16 h0 = __float2bfloat16(x0);
            __nv_bfloat16 h1 = __float2bfloat16(x1);
            Bhi[n * WST + k2] = pkbf2(h0, h1);
            __nv_bfloat16 l0 = __float2bfloat16(x0 - __bfloat162float(h0));
            __nv_bfloat16 l1 = __float2bfloat16(x1 - __bfloat162float(h1));
            Blo[n * WST + k2] = pkbf2(l0, l1);
        }
        __syncthreads();

        float acc[4][4][4];
        #pragma unroll
        for (int ms = 0; ms < 4; ms++)
            #pragma unroll
            for (int ns = 0; ns < 4; ns++)
                #pragma unroll
                for (int x = 0; x < 4; x++) acc[ms][ns][x] = 0.0f;

        #pragma unroll
        for (int ks = 0; ks < 8; ks++) {
            const int kw = ks * 8 + q;
            unsigned ah[4][4], al[4][4], bh[4][2], bl[4][2];
            #pragma unroll
            for (int ms = 0; ms < 4; ms++) {
                int r = wm * 64 + ms * 16 + g;
                ah[ms][0] = Ahi[r * WST + kw];
                ah[ms][1] = Ahi[(r + 8) * WST + kw];
                ah[ms][2] = Ahi[r * WST + kw + 4];
                ah[ms][3] = Ahi[(r + 8) * WST + kw + 4];
                al[ms][0] = Alo[r * WST + kw];
                al[ms][1] = Alo[(r + 8) * WST + kw];
                al[ms][2] = Alo[r * WST + kw + 4];
                al[ms][3] = Alo[(r + 8) * WST + kw + 4];
            }
            #pragma unroll
            for (int ns = 0; ns < 4; ns++) {
                int c = wn * 32 + ns * 8 + g;
                bh[ns][0] = Bhi[c * WST + kw];
                bh[ns][1] = Bhi[c * WST + kw + 4];
                bl[ns][0] = Blo[c * WST + kw];
                bl[ns][1] = Blo[c * WST + kw + 4];
            }
            #pragma unroll
            for (int ms = 0; ms < 4; ms++)
                #pragma unroll
                for (int ns = 0; ns < 4; ns++) {
                    MMA16816(acc[ms][ns], ah[ms], bh[ns]);
                    MMA16816(acc[ms][ns], al[ms], bh[ns]);
                    MMA16816(acc[ms][ns], ah[ms], bl[ns]);
                }
        }

        // ---- Epilogue: add bias, store ----
        #pragma unroll
        for (int ns = 0; ns < 4; ns++) {
            int c = n0 + wn * 32 + ns * 8 + 2 * q;
            float b0 = bias[c], b1 = bias[c + 1];
            #pragma unroll
            for (int ms = 0; ms < 4; ms++) {
                int rg = m0 + wm * 64 + ms * 16 + g;
                float2 v0 = make_float2(acc[ms][ns][0] + b0,
                                        acc[ms][ns][1] + b1);
                float2 v1 = make_float2(acc[ms][ns][2] + b0,
                                        acc[ms][ns][3] + b1);
                *reinterpret_cast<float2*>(g_gi + (size_t)rg * GI_COLS + c) = v0;
                *reinterpret_cast<float2*>(
                    g_gi + (size_t)(rg + 8) * GI_COLS + c) = v1;
            }
        }
    }
}

// ---------------------------------------------------------------------------
// Phase 2: sequential GRU scan (unchanged from R8 winner). 128 CTAs x 512
// threads, 2 envs/CTA; register-resident hidden weights; gi staged one step
// ahead via cp.async; resets in SMEM table.
// ---------------------------------------------------------------------------
__global__ __launch_bounds__(512, 1)
void gru_scan_kernel(const float* __restrict__ hidden0,
                     const unsigned char* __restrict__ resets_raw,
                     const float* __restrict__ Whr,
                     const float* __restrict__ Whz,
                     const float* __restrict__ Whn,
                     const float* __restrict__ bhn,
                     float* __restrict__ out_final,
                     float* __restrict__ out_ys) {
    __shared__ __align__(16) float hsm[2][FEAT];
    __shared__ float part[2][3][4][FEAT];       // [env][gate][kgroup][f]
    __shared__ __align__(16) float gibuf[2][2 * GI_COLS];
    __shared__ unsigned char rs2[T_STEPS * 2];  // [t][env]

    const int tid = threadIdx.x;
    const int f   = tid & 127;
    const int kg  = tid >> 7;       // 0..3
    const int k0  = kg * 32;
    const int envBase = blockIdx.x * 2;

    int local = 0;
    for (int i = tid; i < 4096; i += 512)
        if ((i & 3) != 0 && resets_raw[i] != 0) local = 1;
    const bool bmode = __syncthreads_or(local);
    const int* resets_i = reinterpret_cast<const int*>(resets_raw);

    const unsigned gib0 = smem_u32(&gibuf[0][0]);
    const unsigned gib1 = smem_u32(&gibuf[1][0]);
    if (tid < 192) {
        const float* src = g_gi + (size_t)envBase * GI_COLS + tid * 4;
        CP_ASYNC16(gib0 + tid * 16, src);
        CP_COMMIT();
    }

    for (int i = tid; i < T_STEPS * 2; i += 512) {
        int tt = i >> 1, e = i & 1;
        int gidx = tt * NENV + envBase + e;
        rs2[i] = bmode ? (resets_raw[gidx] != 0) : (resets_i[gidx] != 0);
    }

    ull wr2[16], wz2[16], wn2[16];
    #pragma unroll
    for (int j = 0; j < 16; j++) {
        int k = k0 + 2 * j;
        wr2[j] = pack2(Whr[k * FEAT + f], Whr[(k + 1) * FEAT + f]);
        wz2[j] = pack2(Whz[k * FEAT + f], Whz[(k + 1) * FEAT + f]);
        wn2[j] = pack2(Whn[k * FEAT + f], Whn[(k + 1) * FEAT + f]);
    }
    const float bn = bhn[f];
    __syncthreads();   // rs2 visible

    if (kg < 2) {
        int e = kg, env = envBase + e;
        float h0 = hidden0[env * FEAT + f];
        hsm[e][f] = rs2[e] ? 0.0f : h0;
    }
    __syncthreads();

    float finalh = 0.0f;

    #pragma unroll 1
    for (int t = 0; t < T_STEPS; t++) {
        const int p = t & 1;

        if (tid < 192) {
            int tn = (t + 1 < T_STEPS) ? (t + 1) : t;
            const float* src =
                g_gi + ((size_t)tn * NENV + envBase) * GI_COLS + tid * 4;
            CP_ASYNC16((p ? gib0 : gib1) + tid * 16, src);
            CP_COMMIT();
        }

        #pragma unroll
        for (int e = 0; e < 2; e++) {
            ull ar = 0ull, az = 0ull, an = 0ull;
            const ull* h64 = reinterpret_cast<const ull*>(&hsm[e][k0]);
            #pragma unroll
            for (int j = 0; j < 16; j++) {
                ull h2 = h64[j];
                FMA2(ar, h2, wr2[j], ar);
                FMA2(az, h2, wz2[j], az);
                FMA2(an, h2, wn2[j], an);
            }
            float lo, hi;
            unpack2(lo, hi, ar); part[e][0][kg][f] = lo + hi;
            unpack2(lo, hi, az); part[e][1][kg][f] = lo + hi;
            unpack2(lo, hi, an); part[e][2][kg][f] = lo + hi;
        }
        if (tid < 192) CP_WAIT1();
        __syncthreads();

        if (kg < 2) {
            int e = kg, env = envBase + e;
            const float* gb = &gibuf[p][e * GI_COLS];
            float gr = gb[f], gz = gb[FEAT + f], gn = gb[2 * FEAT + f];
            float sr = part[e][0][0][f] + part[e][0][1][f] +
                       part[e][0][2][f] + part[e][0][3][f];
            float sz = part[e][1][0][f] + part[e][1][1][f] +
                       part[e][1][2][f] + part[e][1][3][f];
            float sn = part[e][2][0][f] + part[e][2][1][f] +
                       part[e][2][2][f] + part[e][2][3][f];
            float r = sigmoidapx(gr + sr);
            float z = sigmoidapx(gz + sz);
            float n = tanhapx(gn + r * (sn + bn));
            float hold = hsm[e][f];
            float hnew = (1.0f - z) * n + z * hold;
            out_ys[(size_t)(t * NENV + env) * FEAT + f] = hnew;
            bool nextdone = (t + 1 < T_STEPS) ? (rs2[(t + 1) * 2 + e] != 0)
                                              : false;
            hsm[e][f] = nextdone ? 0.0f : hnew;
            if (t == T_STEPS - 1) finalh = hnew;
        }
        __syncthreads();
    }

    if (kg < 2) {
        int env = envBase + kg;
        out_final[env * FEAT + f] = finalh;
    }
}

// ---------------------------------------------------------------------------
// Launch
// Inputs: 0 hidden_state [N,F], 1 obs [T,N,D], 2 resets [T,N] (bool/int32),
//         3 Wi [D,3F], 4 bi [3F], 5 Whr, 6 Whz, 7 Whn [F,F], 8 bhn [F]
// Output: final_h [N,F] followed by ys [T,N,F]
// ---------------------------------------------------------------------------
extern "C" void kernel_launch(void* const* d_in, const int* in_sizes, int n_in,
                              void* d_out, int out_size) {
    const float*         hidden = (const float*)d_in[0];
    const float*         obs    = (const float*)d_in[1];
    const unsigned char* resets = (const unsigned char*)d_in[2];
    const float*         Wi     = (const float*)d_in[3];
    const float*         bi     = (const float*)d_in[4];
    const float*         Whr    = (const float*)d_in[5];
    const float*         Whz    = (const float*)d_in[6];
    const float*         Whn    = (const float*)d_in[7];
    const float*         bhn    = (const float*)d_in[8];

    float* out       = (float*)d_out;
    float* out_final = out;                       // [N*F]
    float* out_ys    = out + NENV * FEAT;         // [T*N*F]

    const int smem_bytes = 4 * 128 * WST * (int)sizeof(unsigned);  // 139264
    static int attr_set = 0;
    if (!attr_set) {
        cudaFuncSetAttribute(gemm_gi_bf16_kernel,
                             cudaFuncAttributeMaxDynamicSharedMemorySize,
                             smem_bytes);
        attr_set = 1;
    }

    gemm_gi_bf16_kernel<<<(T_STEPS * NENV) / 128, 256, smem_bytes>>>(obs, Wi, bi);

    gru_scan_kernel<<<NENV / 2, 512>>>(hidden, resets, Whr, Whz, Whn, bhn,
                                       out_final, out_ys);
}